// round 12
// baseline (speedup 1.0000x reference)
#include <cuda_runtime.h>
#include <math.h>

// ---- problem shapes ----
#define BATCH  32
#define CIN    512
#define HW     196
#define DPROJ  8192
#define DMASK  8191
#define NPAIR  (CIN * CIN)         // 262144

// ---- GEMM tiling ----
#define KT     49                  // K sub-tile (4*49 = 196)
#define NKT    4
#define ASTR   260                 // dup-packed A row stride: 2*128 + 4
#define BSTR   132                 // B row stride: 128 + 4

typedef unsigned long long ull;

// ---- device scratch (static, no allocations) ----
__device__ int   d_h[2][CIN];
__device__ float d_s[2][CIN];
__device__ float d_G[(size_t)BATCH * CIN * CIN];   // 32 MB
__device__ int   d_cnt[DPROJ];
__device__ int   d_off[DPROJ + 1];
__device__ int   d_cur[DPROJ];
__device__ int   d_list[NPAIR];
__device__ float d_yacc[BATCH * DPROJ];
__device__ float d_norm[BATCH];

__device__ __forceinline__ ull ffma2(ull a, ull b, ull c) {
    ull d; asm("fma.rn.f32x2 %0, %1, %2, %3;" : "=l"(d) : "l"(a), "l"(b), "l"(c));
    return d;
}
__device__ __forceinline__ void unpack2(ull v, float& x, float& y) {
    asm("mov.b64 {%0, %1}, %2;" : "=f"(x), "=f"(y) : "l"(v));
}

// ============================================================
// 1a/1b: extract count-sketch (h, s) from dense S1/S2.
// ============================================================
__global__ void extract_one(const float* __restrict__ S, int m) {
    int r    = (blockIdx.x << 3) + (threadIdx.x >> 5);   // 512 rows
    int lane = threadIdx.x & 31;
    const float4* S4 = (const float4*)(S + (size_t)r * DPROJ);
    for (int i = lane; i < DPROJ / 4; i += 32) {
        float4 v = S4[i];
        int base = i << 2;
        if (v.x != 0.f) { d_h[m][r] = base + 0; d_s[m][r] = v.x; }
        if (v.y != 0.f) { d_h[m][r] = base + 1; d_s[m][r] = v.y; }
        if (v.z != 0.f) { d_h[m][r] = base + 2; d_s[m][r] = v.z; }
        if (v.w != 0.f) { d_h[m][r] = base + 3; d_s[m][r] = v.w; }
    }
}

// ============================================================
// 2: zero histogram + norms (graph is replayed; must re-init).
// ============================================================
__global__ void zero_kernel() {
    int g = blockIdx.x * blockDim.x + threadIdx.x;      // 8192 threads
    d_cnt[g] = 0;
    if (g < BATCH) d_norm[g] = 0.f;
}

// ============================================================
// 3: histogram pairs by bin. 256 CTAs x 256 thr x 4 pairs.
// ============================================================
__global__ void count_kernel() {
    int p0 = (blockIdx.x * blockDim.x + threadIdx.x) << 2;
    int c1 = p0 >> 9;
    int h1 = d_h[0][c1];
#pragma unroll
    for (int e = 0; e < 4; ++e) {
        int c2 = (p0 + e) & 511;
        atomicAdd(&d_cnt[(h1 + d_h[1][c2]) & DMASK], 1);
    }
}

// ============================================================
// 4: exclusive scan of the 8192-bin histogram (single CTA).
// ============================================================
__global__ void scan_kernel() {
    __shared__ int ws[32];
    const int tid  = threadIdx.x;                       // 1024 threads
    const int lane = tid & 31;
    const int wid  = tid >> 5;
    const int base = tid * 8;
    int v[8], tsum = 0;
#pragma unroll
    for (int e = 0; e < 8; ++e) { v[e] = d_cnt[base + e]; tsum += v[e]; }
    // warp inclusive scan of per-thread sums
    int inc = tsum;
#pragma unroll
    for (int o = 1; o < 32; o <<= 1) {
        int t = __shfl_up_sync(0xFFFFFFFFu, inc, o);
        if (lane >= o) inc += t;
    }
    int exc = inc - tsum;
    if (lane == 31) ws[wid] = inc;
    __syncthreads();
    if (wid == 0) {
        int w = ws[lane];
        int wi = w;
#pragma unroll
        for (int o = 1; o < 32; o <<= 1) {
            int t = __shfl_up_sync(0xFFFFFFFFu, wi, o);
            if (lane >= o) wi += t;
        }
        ws[lane] = wi - w;                              // exclusive
    }
    __syncthreads();
    int run = ws[wid] + exc;
#pragma unroll
    for (int e = 0; e < 8; ++e) {
        d_off[base + e] = run;
        d_cur[base + e] = run;
        run += v[e];
    }
    if (tid == 0) d_off[DPROJ] = NPAIR;
}

// ============================================================
// 5: fill bin-sorted pair list.
// ============================================================
__global__ void fill_kernel() {
    int p0 = (blockIdx.x * blockDim.x + threadIdx.x) << 2;
    int c1 = p0 >> 9;
    int h1 = d_h[0][c1];
#pragma unroll
    for (int e = 0; e < 4; ++e) {
        int p  = p0 + e;
        int c2 = p & 511;
        int pos = atomicAdd(&d_cur[(h1 + d_h[1][c2]) & DMASK], 1);
        d_list[pos] = p;                                // p = c1*512 + c2
    }
}

// ============================================================
// 6: batched sign-folded Gram GEMM.
// grid (16 tiles, 32 imgs), 256 thr, tile 128x128, thread 8x8, FFMA2.
// G~[b][c1][c2] = (s1[c1] x[b,c1,:]) . (s2[c2] x[b,c2,:])
// ============================================================
__global__ __launch_bounds__(256, 2)
void gram_gemm(const float* __restrict__ x) {
    extern __shared__ float sm[];
    float* Ad  = sm;                      // KT*ASTR dup-packed
    float* Bs  = Ad + KT * ASTR;          // KT*BSTR

    const int b    = blockIdx.y;
    const int tile = blockIdx.x;
    const int c1_0 = (tile >> 2) * 128;
    const int c2_0 = (tile & 3)  * 128;
    const int tid  = threadIdx.x;
    const int ao   = (tid >> 4) * 8;
    const int bo   = (tid & 15) * 8;

    const float* xb = x + (size_t)b * CIN * HW;

    ull acc[8][4];
#pragma unroll
    for (int i = 0; i < 8; ++i)
#pragma unroll
        for (int j = 0; j < 4; ++j) acc[i][j] = 0ULL;

    for (int kt = 0; kt < NKT; ++kt) {
        const int k0 = kt * KT;
        __syncthreads();
        for (int l = tid; l < 128 * KT; l += 256) {
            int ci = l / KT, k = l - ci * KT;
            float v = xb[(c1_0 + ci) * HW + k0 + k] * d_s[0][c1_0 + ci];
            float2 vv; vv.x = v; vv.y = v;
            *(float2*)&Ad[k * ASTR + 2 * ci] = vv;
        }
        for (int l = tid; l < 128 * KT; l += 256) {
            int ci = l / KT, k = l - ci * KT;
            Bs[k * BSTR + ci] = xb[(c2_0 + ci) * HW + k0 + k] * d_s[1][c2_0 + ci];
        }
        __syncthreads();
#pragma unroll 7
        for (int k = 0; k < KT; ++k) {
            const float* Ar = Ad + k * ASTR + 2 * ao;
            ulonglong2 a01 = *(const ulonglong2*)(Ar);
            ulonglong2 a23 = *(const ulonglong2*)(Ar + 4);
            ulonglong2 a45 = *(const ulonglong2*)(Ar + 8);
            ulonglong2 a67 = *(const ulonglong2*)(Ar + 12);
            const float* Br = Bs + k * BSTR + bo;
            ulonglong2 bb0 = *(const ulonglong2*)(Br);        // cols 0-3
            ulonglong2 bb1 = *(const ulonglong2*)(Br + 4);    // cols 4-7
            acc[0][0] = ffma2(a01.x, bb0.x, acc[0][0]);
            acc[0][1] = ffma2(a01.x, bb0.y, acc[0][1]);
            acc[0][2] = ffma2(a01.x, bb1.x, acc[0][2]);
            acc[0][3] = ffma2(a01.x, bb1.y, acc[0][3]);
            acc[1][0] = ffma2(a01.y, bb0.x, acc[1][0]);
            acc[1][1] = ffma2(a01.y, bb0.y, acc[1][1]);
            acc[1][2] = ffma2(a01.y, bb1.x, acc[1][2]);
            acc[1][3] = ffma2(a01.y, bb1.y, acc[1][3]);
            acc[2][0] = ffma2(a23.x, bb0.x, acc[2][0]);
            acc[2][1] = ffma2(a23.x, bb0.y, acc[2][1]);
            acc[2][2] = ffma2(a23.x, bb1.x, acc[2][2]);
            acc[2][3] = ffma2(a23.x, bb1.y, acc[2][3]);
            acc[3][0] = ffma2(a23.y, bb0.x, acc[3][0]);
            acc[3][1] = ffma2(a23.y, bb0.y, acc[3][1]);
            acc[3][2] = ffma2(a23.y, bb1.x, acc[3][2]);
            acc[3][3] = ffma2(a23.y, bb1.y, acc[3][3]);
            acc[4][0] = ffma2(a45.x, bb0.x, acc[4][0]);
            acc[4][1] = ffma2(a45.x, bb0.y, acc[4][1]);
            acc[4][2] = ffma2(a45.x, bb1.x, acc[4][2]);
            acc[4][3] = ffma2(a45.x, bb1.y, acc[4][3]);
            acc[5][0] = ffma2(a45.y, bb0.x, acc[5][0]);
            acc[5][1] = ffma2(a45.y, bb0.y, acc[5][1]);
            acc[5][2] = ffma2(a45.y, bb1.x, acc[5][2]);
            acc[5][3] = ffma2(a45.y, bb1.y, acc[5][3]);
            acc[6][0] = ffma2(a67.x, bb0.x, acc[6][0]);
            acc[6][1] = ffma2(a67.x, bb0.y, acc[6][1]);
            acc[6][2] = ffma2(a67.x, bb1.x, acc[6][2]);
            acc[6][3] = ffma2(a67.x, bb1.y, acc[6][3]);
            acc[7][0] = ffma2(a67.y, bb0.x, acc[7][0]);
            acc[7][1] = ffma2(a67.y, bb0.y, acc[7][1]);
            acc[7][2] = ffma2(a67.y, bb1.x, acc[7][2]);
            acc[7][3] = ffma2(a67.y, bb1.y, acc[7][3]);
        }
    }

    // epilogue: coalesced stores into d_G[b][c1][c2]
    float* Gb = d_G + ((size_t)b << 18);
#pragma unroll
    for (int i = 0; i < 8; ++i) {
        float c0, c1f, c2f, c3, c4, c5, c6, c7;
        unpack2(acc[i][0], c0, c1f);
        unpack2(acc[i][1], c2f, c3);
        unpack2(acc[i][2], c4, c5);
        unpack2(acc[i][3], c6, c7);
        float* g = Gb + (size_t)(c1_0 + ao + i) * CIN + c2_0 + bo;
        float4 w0; w0.x = c0; w0.y = c1f; w0.z = c2f; w0.w = c3;
        float4 w1; w1.x = c4; w1.y = c5;  w1.z = c6;  w1.w = c7;
        *(float4*)(g)     = w0;
        *(float4*)(g + 4) = w1;
    }
}

// ============================================================
// 7: gather — one warp per (bin, image). No atomics.
// ============================================================
__global__ __launch_bounds__(256, 8)
void gather_kernel() {
    const int b    = blockIdx.y;
    const int d    = (blockIdx.x << 3) + (threadIdx.x >> 5);
    const int lane = threadIdx.x & 31;
    const int o0 = d_off[d];
    const int o1 = d_off[d + 1];
    const float* Gb = d_G + ((size_t)b << 18);
    float s = 0.f;
    for (int p = o0 + lane; p < o1; p += 32) s += Gb[d_list[p]];
#pragma unroll
    for (int o = 16; o; o >>= 1) s += __shfl_xor_sync(0xFFFFFFFFu, s, o);
    if (lane == 0) d_yacc[b * DPROJ + d] = s;
}

// ============================================================
// 8: signed sqrt, write out, accumulate per-image sum-of-squares.
// ============================================================
__global__ void finalize1(float* __restrict__ out) {
    __shared__ float red[8];
    const int img = blockIdx.x >> 3;
    const int chunk = blockIdx.x & 7;
    const int tid = threadIdx.x;
    const float4* yb = (const float4*)(d_yacc + (size_t)img * DPROJ + chunk * 1024);
    float4* ob = (float4*)(out + (size_t)img * DPROJ + chunk * 1024);

    float4 v = yb[tid];
    float4 t;
    float* vp = (float*)&v;
    float* tp = (float*)&t;
    float ss = 0.f;
#pragma unroll
    for (int c = 0; c < 4; ++c) {
        float vv = vp[c], tt;
        if      (vv > 0.f) tt =  sqrtf( vv + 1e-8f);
        else if (vv < 0.f) tt = -sqrtf(-vv + 1e-8f);
        else               tt = 0.f;
        tp[c] = tt;
        ss += tt * tt;
    }
    ob[tid] = t;
#pragma unroll
    for (int o = 16; o; o >>= 1) ss += __shfl_xor_sync(0xFFFFFFFFu, ss, o);
    if ((tid & 31) == 0) red[tid >> 5] = ss;
    __syncthreads();
    if (tid == 0) {
        float s = 0.f;
#pragma unroll
        for (int i = 0; i < 8; ++i) s += red[i];
        atomicAdd(&d_norm[img], s);
    }
}

// ============================================================
// 9: scale by 1/max(||y||, 1e-12).
// ============================================================
__global__ void finalize2(float* __restrict__ out) {
    const int img = blockIdx.x >> 3;
    const int chunk = blockIdx.x & 7;
    const int tid = threadIdx.x;
    float inv = 1.f / fmaxf(sqrtf(d_norm[img]), 1e-12f);
    float4* ob = (float4*)(out + (size_t)img * DPROJ + chunk * 1024);
    float4 v = ob[tid];
    v.x *= inv; v.y *= inv; v.z *= inv; v.w *= inv;
    ob[tid] = v;
}

// ============================================================
extern "C" void kernel_launch(void* const* d_in, const int* in_sizes, int n_in,
                              void* d_out, int out_size) {
    (void)in_sizes; (void)n_in; (void)out_size;
    const float* x  = (const float*)d_in[0];
    const float* S1 = (const float*)d_in[1];
    const float* S2 = (const float*)d_in[2];
    float* out = (float*)d_out;

    const int gemm_smem = (KT * ASTR + KT * BSTR) * (int)sizeof(float);  // 76832
    cudaFuncSetAttribute(gram_gemm,
                         cudaFuncAttributeMaxDynamicSharedMemorySize, gemm_smem);

    extract_one<<<64, 256>>>(S1, 0);
    extract_one<<<64, 256>>>(S2, 1);
    zero_kernel<<<32, 256>>>();
    count_kernel<<<256, 256>>>();
    scan_kernel<<<1, 1024>>>();
    fill_kernel<<<256, 256>>>();
    gram_gemm<<<dim3(16, BATCH), 256, gemm_smem>>>(x);
    gather_kernel<<<dim3(1024, BATCH), 256>>>();
    finalize1<<<BATCH * 8, 256>>>(out);
    finalize2<<<BATCH * 8, 256>>>(out);
}

// round 14
// speedup vs baseline: 1.0989x; 1.0989x over previous
#include <cuda_runtime.h>
#include <math.h>

// ---- problem shapes ----
#define BATCH  32
#define CIN    512
#define HW     196
#define DPROJ  8192
#define DMASK  8191
#define NPAIR  (CIN * CIN)         // 262144

// ---- GEMM tiling ----
#define KT     49                  // K sub-tile (4*49 = 196)
#define NKT    4
#define ASTR   260                 // dup-packed A row stride: 2*128 + 4
#define BSTR   132                 // B row stride: 128 + 4

typedef unsigned long long ull;

// ---- device scratch (static, no allocations) ----
__device__ int   d_h[2][CIN];
__device__ float d_s[2][CIN];
__device__ float d_G [(size_t)BATCH * NPAIR];      // [b][p]  32 MB
__device__ float d_Gt[(size_t)NPAIR * BATCH];      // [p][b]  32 MB
__device__ int   d_cnt[DPROJ];
__device__ int   d_off[DPROJ + 1];
__device__ int   d_cur[DPROJ];
__device__ int   d_list[NPAIR];
__device__ float d_yacc[BATCH * DPROJ];
__device__ float d_norm[BATCH];

__device__ __forceinline__ ull ffma2(ull a, ull b, ull c) {
    ull d; asm("fma.rn.f32x2 %0, %1, %2, %3;" : "=l"(d) : "l"(a), "l"(b), "l"(c));
    return d;
}
__device__ __forceinline__ void unpack2(ull v, float& x, float& y) {
    asm("mov.b64 {%0, %1}, %2;" : "=f"(x), "=f"(y) : "l"(v));
}

// ============================================================
// 1a/1b: extract count-sketch (h, s) from dense S1/S2.
// ============================================================
__global__ void extract_one(const float* __restrict__ S, int m) {
    int r    = (blockIdx.x << 3) + (threadIdx.x >> 5);   // 512 rows
    int lane = threadIdx.x & 31;
    const float4* S4 = (const float4*)(S + (size_t)r * DPROJ);
    for (int i = lane; i < DPROJ / 4; i += 32) {
        float4 v = S4[i];
        int base = i << 2;
        if (v.x != 0.f) { d_h[m][r] = base + 0; d_s[m][r] = v.x; }
        if (v.y != 0.f) { d_h[m][r] = base + 1; d_s[m][r] = v.y; }
        if (v.z != 0.f) { d_h[m][r] = base + 2; d_s[m][r] = v.z; }
        if (v.w != 0.f) { d_h[m][r] = base + 3; d_s[m][r] = v.w; }
    }
}

// ============================================================
// 2: zero histogram + norms (graph is replayed; must re-init).
// ============================================================
__global__ void zero_kernel() {
    int g = blockIdx.x * blockDim.x + threadIdx.x;      // 8192 threads
    d_cnt[g] = 0;
    if (g < BATCH) d_norm[g] = 0.f;
}

// ============================================================
// 3: batched sign-folded Gram GEMM.  (4th launch -> ncu target)
// grid (16 tiles, 32 imgs), 256 thr, tile 128x128, thread 8x8, FFMA2.
// ============================================================
__global__ __launch_bounds__(256, 2)
void gram_gemm(const float* __restrict__ x) {
    extern __shared__ float sm[];
    float* Ad  = sm;                      // KT*ASTR dup-packed
    float* Bs  = Ad + KT * ASTR;          // KT*BSTR

    const int b    = blockIdx.y;
    const int tile = blockIdx.x;
    const int c1_0 = (tile >> 2) * 128;
    const int c2_0 = (tile & 3)  * 128;
    const int tid  = threadIdx.x;
    const int ao   = (tid >> 4) * 8;
    const int bo   = (tid & 15) * 8;

    const float* xb = x + (size_t)b * CIN * HW;

    ull acc[8][4];
#pragma unroll
    for (int i = 0; i < 8; ++i)
#pragma unroll
        for (int j = 0; j < 4; ++j) acc[i][j] = 0ULL;

    for (int kt = 0; kt < NKT; ++kt) {
        const int k0 = kt * KT;
        __syncthreads();
        for (int l = tid; l < 128 * KT; l += 256) {
            int ci = l / KT, k = l - ci * KT;
            float v = xb[(c1_0 + ci) * HW + k0 + k] * d_s[0][c1_0 + ci];
            float2 vv; vv.x = v; vv.y = v;
            *(float2*)&Ad[k * ASTR + 2 * ci] = vv;
        }
        for (int l = tid; l < 128 * KT; l += 256) {
            int ci = l / KT, k = l - ci * KT;
            Bs[k * BSTR + ci] = xb[(c2_0 + ci) * HW + k0 + k] * d_s[1][c2_0 + ci];
        }
        __syncthreads();
#pragma unroll 7
        for (int k = 0; k < KT; ++k) {
            const float* Ar = Ad + k * ASTR + 2 * ao;
            ulonglong2 a01 = *(const ulonglong2*)(Ar);
            ulonglong2 a23 = *(const ulonglong2*)(Ar + 4);
            ulonglong2 a45 = *(const ulonglong2*)(Ar + 8);
            ulonglong2 a67 = *(const ulonglong2*)(Ar + 12);
            const float* Br = Bs + k * BSTR + bo;
            ulonglong2 bb0 = *(const ulonglong2*)(Br);
            ulonglong2 bb1 = *(const ulonglong2*)(Br + 4);
            acc[0][0] = ffma2(a01.x, bb0.x, acc[0][0]);
            acc[0][1] = ffma2(a01.x, bb0.y, acc[0][1]);
            acc[0][2] = ffma2(a01.x, bb1.x, acc[0][2]);
            acc[0][3] = ffma2(a01.x, bb1.y, acc[0][3]);
            acc[1][0] = ffma2(a01.y, bb0.x, acc[1][0]);
            acc[1][1] = ffma2(a01.y, bb0.y, acc[1][1]);
            acc[1][2] = ffma2(a01.y, bb1.x, acc[1][2]);
            acc[1][3] = ffma2(a01.y, bb1.y, acc[1][3]);
            acc[2][0] = ffma2(a23.x, bb0.x, acc[2][0]);
            acc[2][1] = ffma2(a23.x, bb0.y, acc[2][1]);
            acc[2][2] = ffma2(a23.x, bb1.x, acc[2][2]);
            acc[2][3] = ffma2(a23.x, bb1.y, acc[2][3]);
            acc[3][0] = ffma2(a23.y, bb0.x, acc[3][0]);
            acc[3][1] = ffma2(a23.y, bb0.y, acc[3][1]);
            acc[3][2] = ffma2(a23.y, bb1.x, acc[3][2]);
            acc[3][3] = ffma2(a23.y, bb1.y, acc[3][3]);
            acc[4][0] = ffma2(a45.x, bb0.x, acc[4][0]);
            acc[4][1] = ffma2(a45.x, bb0.y, acc[4][1]);
            acc[4][2] = ffma2(a45.x, bb1.x, acc[4][2]);
            acc[4][3] = ffma2(a45.x, bb1.y, acc[4][3]);
            acc[5][0] = ffma2(a45.y, bb0.x, acc[5][0]);
            acc[5][1] = ffma2(a45.y, bb0.y, acc[5][1]);
            acc[5][2] = ffma2(a45.y, bb1.x, acc[5][2]);
            acc[5][3] = ffma2(a45.y, bb1.y, acc[5][3]);
            acc[6][0] = ffma2(a67.x, bb0.x, acc[6][0]);
            acc[6][1] = ffma2(a67.x, bb0.y, acc[6][1]);
            acc[6][2] = ffma2(a67.x, bb1.x, acc[6][2]);
            acc[6][3] = ffma2(a67.x, bb1.y, acc[6][3]);
            acc[7][0] = ffma2(a67.y, bb0.x, acc[7][0]);
            acc[7][1] = ffma2(a67.y, bb0.y, acc[7][1]);
            acc[7][2] = ffma2(a67.y, bb1.x, acc[7][2]);
            acc[7][3] = ffma2(a67.y, bb1.y, acc[7][3]);
        }
    }

    float* Gb = d_G + ((size_t)b << 18);
#pragma unroll
    for (int i = 0; i < 8; ++i) {
        float c0, c1f, c2f, c3, c4, c5, c6, c7;
        unpack2(acc[i][0], c0, c1f);
        unpack2(acc[i][1], c2f, c3);
        unpack2(acc[i][2], c4, c5);
        unpack2(acc[i][3], c6, c7);
        float* g = Gb + (size_t)(c1_0 + ao + i) * CIN + c2_0 + bo;
        float4 w0; w0.x = c0; w0.y = c1f; w0.z = c2f; w0.w = c3;
        float4 w1; w1.x = c4; w1.y = c5;  w1.z = c6;  w1.w = c7;
        *(float4*)(g)     = w0;
        *(float4*)(g + 4) = w1;
    }
}

// ============================================================
// 4: histogram pairs by bin.
// ============================================================
__global__ void count_kernel() {
    int p0 = (blockIdx.x * blockDim.x + threadIdx.x) << 2;
    int c1 = p0 >> 9;
    int h1 = d_h[0][c1];
#pragma unroll
    for (int e = 0; e < 4; ++e) {
        int c2 = (p0 + e) & 511;
        atomicAdd(&d_cnt[(h1 + d_h[1][c2]) & DMASK], 1);
    }
}

// ============================================================
// 5: exclusive scan of the 8192-bin histogram (single CTA).
// ============================================================
__global__ void scan_kernel() {
    __shared__ int ws[32];
    const int tid  = threadIdx.x;                       // 1024 threads
    const int lane = tid & 31;
    const int wid  = tid >> 5;
    const int base = tid * 8;
    int v[8], tsum = 0;
#pragma unroll
    for (int e = 0; e < 8; ++e) { v[e] = d_cnt[base + e]; tsum += v[e]; }
    int inc = tsum;
#pragma unroll
    for (int o = 1; o < 32; o <<= 1) {
        int t = __shfl_up_sync(0xFFFFFFFFu, inc, o);
        if (lane >= o) inc += t;
    }
    int exc = inc - tsum;
    if (lane == 31) ws[wid] = inc;
    __syncthreads();
    if (wid == 0) {
        int w = ws[lane];
        int wi = w;
#pragma unroll
        for (int o = 1; o < 32; o <<= 1) {
            int t = __shfl_up_sync(0xFFFFFFFFu, wi, o);
            if (lane >= o) wi += t;
        }
        ws[lane] = wi - w;
    }
    __syncthreads();
    int run = ws[wid] + exc;
#pragma unroll
    for (int e = 0; e < 8; ++e) {
        d_off[base + e] = run;
        d_cur[base + e] = run;
        run += v[e];
    }
    if (tid == 0) d_off[DPROJ] = NPAIR;
}

// ============================================================
// 6: fill bin-sorted pair list.
// ============================================================
__global__ void fill_kernel() {
    int p0 = (blockIdx.x * blockDim.x + threadIdx.x) << 2;
    int c1 = p0 >> 9;
    int h1 = d_h[0][c1];
#pragma unroll
    for (int e = 0; e < 4; ++e) {
        int p  = p0 + e;
        int c2 = p & 511;
        int pos = atomicAdd(&d_cur[(h1 + d_h[1][c2]) & DMASK], 1);
        d_list[pos] = p;
    }
}

// ============================================================
// 7: transpose G[b][p] -> Gt[p][b] via 32x64 smem tiles.
// Coalesced reads and writes; conflict-free stride-33 tile.
// ============================================================
__global__ __launch_bounds__(256, 8)
void transpose_kernel() {
    __shared__ float T[64 * 33];
    const int p0  = blockIdx.x << 6;          // 4096 CTAs x 64 pairs
    const int tid = threadIdx.x;

    // load: b = tid>>3 (0..31), j0 = (tid&7)*8 -> 8 consecutive p
    {
        const int b  = tid >> 3;
        const int j0 = (tid & 7) << 3;
        const float* src = d_G + (size_t)b * NPAIR + p0 + j0;
        float4 v0 = *(const float4*)(src);
        float4 v1 = *(const float4*)(src + 4);
        T[(j0 + 0) * 33 + b] = v0.x;
        T[(j0 + 1) * 33 + b] = v0.y;
        T[(j0 + 2) * 33 + b] = v0.z;
        T[(j0 + 3) * 33 + b] = v0.w;
        T[(j0 + 4) * 33 + b] = v1.x;
        T[(j0 + 5) * 33 + b] = v1.y;
        T[(j0 + 6) * 33 + b] = v1.z;
        T[(j0 + 7) * 33 + b] = v1.w;
    }
    __syncthreads();
    // write: pr = tid>>2 (0..63), b0 = (tid&3)*8 -> 8 consecutive b
    {
        const int pr = tid >> 2;
        const int b0 = (tid & 3) << 3;
        float4 w0, w1;
        w0.x = T[pr * 33 + b0 + 0];
        w0.y = T[pr * 33 + b0 + 1];
        w0.z = T[pr * 33 + b0 + 2];
        w0.w = T[pr * 33 + b0 + 3];
        w1.x = T[pr * 33 + b0 + 4];
        w1.y = T[pr * 33 + b0 + 5];
        w1.z = T[pr * 33 + b0 + 6];
        w1.w = T[pr * 33 + b0 + 7];
        float* dst = d_Gt + (size_t)(p0 + pr) * BATCH + b0;
        *(float4*)(dst)     = w0;
        *(float4*)(dst + 4) = w1;
    }
}

// ============================================================
// 8: gather — one warp per bin; lane = image. Every Gt read is a
// fully coalesced 128B line. No atomics anywhere.
// ============================================================
__global__ __launch_bounds__(256, 8)
void gather_kernel() {
    const int d    = (blockIdx.x << 3) + (threadIdx.x >> 5);   // 1024 CTAs
    const int lane = threadIdx.x & 31;
    const int o0 = d_off[d];
    const int o1 = d_off[d + 1];
    float s = 0.f;
    for (int base = o0; base < o1; base += 32) {
        int pi = 0;
        if (base + lane < o1) pi = d_list[base + lane];
        const int m = min(32, o1 - base);
        for (int e = 0; e < m; ++e) {
            int pe = __shfl_sync(0xFFFFFFFFu, pi, e);
            s += d_Gt[(size_t)pe * BATCH + lane];
        }
    }
    d_yacc[lane * DPROJ + d] = s;
}

// ============================================================
// 9: signed sqrt, write out, accumulate per-image sum-of-squares.
// ============================================================
__global__ void finalize1(float* __restrict__ out) {
    __shared__ float red[8];
    const int img = blockIdx.x >> 3;
    const int chunk = blockIdx.x & 7;
    const int tid = threadIdx.x;
    const float4* yb = (const float4*)(d_yacc + (size_t)img * DPROJ + chunk * 1024);
    float4* ob = (float4*)(out + (size_t)img * DPROJ + chunk * 1024);

    float4 v = yb[tid];
    float4 t;
    float* vp = (float*)&v;
    float* tp = (float*)&t;
    float ss = 0.f;
#pragma unroll
    for (int c = 0; c < 4; ++c) {
        float vv = vp[c], tt;
        if      (vv > 0.f) tt =  sqrtf( vv + 1e-8f);
        else if (vv < 0.f) tt = -sqrtf(-vv + 1e-8f);
        else               tt = 0.f;
        tp[c] = tt;
        ss += tt * tt;
    }
    ob[tid] = t;
#pragma unroll
    for (int o = 16; o; o >>= 1) ss += __shfl_xor_sync(0xFFFFFFFFu, ss, o);
    if ((tid & 31) == 0) red[tid >> 5] = ss;
    __syncthreads();
    if (tid == 0) {
        float s = 0.f;
#pragma unroll
        for (int i = 0; i < 8; ++i) s += red[i];
        atomicAdd(&d_norm[img], s);
    }
}

// ============================================================
// 10: scale by 1/max(||y||, 1e-12).
// ============================================================
__global__ void finalize2(float* __restrict__ out) {
    const int img = blockIdx.x >> 3;
    const int chunk = blockIdx.x & 7;
    const int tid = threadIdx.x;
    float inv = 1.f / fmaxf(sqrtf(d_norm[img]), 1e-12f);
    float4* ob = (float4*)(out + (size_t)img * DPROJ + chunk * 1024);
    float4 v = ob[tid];
    v.x *= inv; v.y *= inv; v.z *= inv; v.w *= inv;
    ob[tid] = v;
}

// ============================================================
extern "C" void kernel_launch(void* const* d_in, const int* in_sizes, int n_in,
                              void* d_out, int out_size) {
    (void)in_sizes; (void)n_in; (void)out_size;
    const float* x  = (const float*)d_in[0];
    const float* S1 = (const float*)d_in[1];
    const float* S2 = (const float*)d_in[2];
    float* out = (float*)d_out;

    const int gemm_smem = (KT * ASTR + KT * BSTR) * (int)sizeof(float);
    cudaFuncSetAttribute(gram_gemm,
                         cudaFuncAttributeMaxDynamicSharedMemorySize, gemm_smem);

    extract_one<<<64, 256>>>(S1, 0);                     // 1
    extract_one<<<64, 256>>>(S2, 1);                     // 2
    zero_kernel<<<32, 256>>>();                          // 3
    gram_gemm<<<dim3(16, BATCH), 256, gemm_smem>>>(x);   // 4 <- ncu target
    count_kernel<<<256, 256>>>();                        // 5
    scan_kernel<<<1, 1024>>>();                          // 6
    fill_kernel<<<256, 256>>>();                         // 7
    transpose_kernel<<<NPAIR / 64, 256>>>();             // 8
    gather_kernel<<<DPROJ / 8, 256>>>();                 // 9
    finalize1<<<BATCH * 8, 256>>>(out);                  // 10
    finalize2<<<BATCH * 8, 256>>>(out);                  // 11
}